// round 1
// baseline (speedup 1.0000x reference)
#include <cuda_runtime.h>

// Problem constants (fixed by the dataset)
#define NTOK 2048          // B*T
#define D    1024
#define E    16
#define F    512
#define FS   2048
#define TOPK 2
#define P    (NTOK*TOPK)   // 4096 token-expert pairs

// ---------------- scratch (device globals: no allocations allowed) ----------
__device__ float g_probs[NTOK * E];     // router probs (for deterministic aux)
__device__ float g_topkw[P];            // normalized routing weights per pair
__device__ int   g_topki[P];            // expert id per pair
__device__ float g_sgate[NTOK];         // sigmoid shared gate
__device__ int   g_count[E];
__device__ int   g_offset[E];
__device__ int   g_cursor[E];
__device__ int   g_perm[P];             // grouped-by-expert -> pair index
__device__ float g_h [(size_t)P * F];   // expert hidden (grouped rows)
__device__ float g_y [(size_t)P * D];   // weighted expert outputs (pair-indexed)
__device__ float g_s [(size_t)NTOK * FS]; // shared-expert hidden
__device__ float g_sh[(size_t)NTOK * D];  // shared-expert output

// ---------------- small kernels --------------------------------------------
__global__ void k_zero() {
    int i = threadIdx.x;
    if (i < E) g_count[i] = 0;
}

// one warp per token: router logits, softmax, top-2, shared-gate scalar
__global__ void k_router(const float* __restrict__ x,
                         const float* __restrict__ rw,
                         const float* __restrict__ sgw) {
    int t    = blockIdx.x * 4 + (threadIdx.x >> 5);
    int lane = threadIdx.x & 31;
    if (t >= NTOK) return;
    const float* xr = x + (size_t)t * D;

    float acc[E];
#pragma unroll
    for (int e = 0; e < E; e++) acc[e] = 0.f;
    float sg = 0.f;

    for (int j = lane; j < D; j += 32) {
        float xv = xr[j];
        const float* r = rw + (size_t)j * E;
#pragma unroll
        for (int e = 0; e < E; e++) acc[e] = fmaf(xv, r[e], acc[e]);
        sg = fmaf(xv, sgw[j], sg);
    }
#pragma unroll
    for (int off = 16; off; off >>= 1) {
#pragma unroll
        for (int e = 0; e < E; e++) acc[e] += __shfl_xor_sync(0xffffffffu, acc[e], off);
        sg += __shfl_xor_sync(0xffffffffu, sg, off);
    }
    // softmax (all lanes redundantly)
    float mx = acc[0];
#pragma unroll
    for (int e = 1; e < E; e++) mx = fmaxf(mx, acc[e]);
    float pr[E]; float sum = 0.f;
#pragma unroll
    for (int e = 0; e < E; e++) { pr[e] = __expf(acc[e] - mx); sum += pr[e]; }
    float inv = 1.f / sum;
#pragma unroll
    for (int e = 0; e < E; e++) pr[e] *= inv;

    if (lane < E) g_probs[(size_t)t * E + lane] = pr[lane];

    if (lane == 0) {
        int i1 = 0; float p1 = pr[0];
#pragma unroll
        for (int e = 1; e < E; e++) if (pr[e] > p1) { p1 = pr[e]; i1 = e; }
        int i2 = (i1 == 0) ? 1 : 0; float p2 = pr[i2];
#pragma unroll
        for (int e = 0; e < E; e++)
            if (e != i1 && pr[e] > p2) { p2 = pr[e]; i2 = e; }
        float s2 = p1 + p2; if (s2 < 1e-9f) s2 = 1e-9f;
        g_topkw[t * 2 + 0] = p1 / s2;
        g_topkw[t * 2 + 1] = p2 / s2;
        g_topki[t * 2 + 0] = i1;
        g_topki[t * 2 + 1] = i2;
        atomicAdd(&g_count[i1], 1);
        atomicAdd(&g_count[i2], 1);
        g_sgate[t] = 1.f / (1.f + __expf(-sg));
    }
}

__global__ void k_scan() {
    int s = 0;
    for (int e = 0; e < E; e++) { g_offset[e] = s; g_cursor[e] = s; s += g_count[e]; }
}

__global__ void k_scatter() {
    int p = blockIdx.x * 256 + threadIdx.x;
    if (p >= P) return;
    int e = g_topki[p];
    int pos = atomicAdd(&g_cursor[e], 1);
    g_perm[pos] = p;
}

// ---------------- GEMM tiles: 64x64, K-chunk 16, 256 threads ----------------
// expert gate/up:  H[r, f] = silu(x_r . Wg[e,f,:]) * (x_r . Wu[e,f,:])
__global__ __launch_bounds__(256) void k_expert_gateup(const float* __restrict__ x,
                                                       const float* __restrict__ gup) {
    int e   = blockIdx.z;
    int cnt = g_count[e];
    int r0  = blockIdx.y * 64;
    if (r0 >= cnt) return;
    int base = g_offset[e];
    int f0   = blockIdx.x * 64;

    __shared__ float As[16][68], Bg[16][68], Bu[16][68];
    int tid = threadIdx.x;
    int lm = tid >> 2;               // 0..63
    int lk = (tid & 3) << 2;         // 0,4,8,12
    int row = r0 + lm;
    int token = 0;
    if (row < cnt) token = g_perm[base + row] >> 1;
    const float* xrow = x + (size_t)token * D;
    const float* grow = gup + ((size_t)e * (2 * F) + (f0 + lm)) * D;
    const float* urow = grow + (size_t)F * D;

    int ty = tid >> 4, tx = tid & 15;
    float ag[4][4] = {}, au[4][4] = {};

    for (int k0 = 0; k0 < D; k0 += 16) {
        float4 av = *(const float4*)(xrow + k0 + lk);
        float4 gv = *(const float4*)(grow + k0 + lk);
        float4 uv = *(const float4*)(urow + k0 + lk);
        As[lk+0][lm]=av.x; As[lk+1][lm]=av.y; As[lk+2][lm]=av.z; As[lk+3][lm]=av.w;
        Bg[lk+0][lm]=gv.x; Bg[lk+1][lm]=gv.y; Bg[lk+2][lm]=gv.z; Bg[lk+3][lm]=gv.w;
        Bu[lk+0][lm]=uv.x; Bu[lk+1][lm]=uv.y; Bu[lk+2][lm]=uv.z; Bu[lk+3][lm]=uv.w;
        __syncthreads();
#pragma unroll
        for (int k = 0; k < 16; k++) {
            float4 a4 = *(const float4*)&As[k][ty << 2];
            float4 g4 = *(const float4*)&Bg[k][tx << 2];
            float4 u4 = *(const float4*)&Bu[k][tx << 2];
            float aa[4] = {a4.x, a4.y, a4.z, a4.w};
            float gg[4] = {g4.x, g4.y, g4.z, g4.w};
            float uu[4] = {u4.x, u4.y, u4.z, u4.w};
#pragma unroll
            for (int i = 0; i < 4; i++)
#pragma unroll
                for (int j = 0; j < 4; j++) {
                    ag[i][j] = fmaf(aa[i], gg[j], ag[i][j]);
                    au[i][j] = fmaf(aa[i], uu[j], au[i][j]);
                }
        }
        __syncthreads();
    }
#pragma unroll
    for (int i = 0; i < 4; i++) {
        int r = r0 + (ty << 2) + i;
        if (r < cnt) {
            float* hrow = g_h + (size_t)(base + r) * F + f0 + (tx << 2);
#pragma unroll
            for (int j = 0; j < 4; j++) {
                float g = ag[i][j], u = au[i][j];
                float sig = 1.f / (1.f + __expf(-g));
                hrow[j] = g * sig * u;
            }
        }
    }
}

// expert down:  y[pair, d] = w_pair * (H[r,:] . Wd[e,d,:])
__global__ __launch_bounds__(256) void k_expert_down(const float* __restrict__ dwn) {
    int e   = blockIdx.z;
    int cnt = g_count[e];
    int r0  = blockIdx.y * 64;
    if (r0 >= cnt) return;
    int base = g_offset[e];
    int d0   = blockIdx.x * 64;

    __shared__ float As[16][68], Bs[16][68];
    int tid = threadIdx.x;
    int lm = tid >> 2;
    int lk = (tid & 3) << 2;
    int row = r0 + lm; if (row >= cnt) row = cnt - 1;  // clamp (loads valid mem)
    const float* hrow = g_h + (size_t)(base + row) * F;
    const float* brow = dwn + ((size_t)e * D + d0 + lm) * F;

    int ty = tid >> 4, tx = tid & 15;
    float acc[4][4] = {};

    for (int k0 = 0; k0 < F; k0 += 16) {
        float4 av = *(const float4*)(hrow + k0 + lk);
        float4 bv = *(const float4*)(brow + k0 + lk);
        As[lk+0][lm]=av.x; As[lk+1][lm]=av.y; As[lk+2][lm]=av.z; As[lk+3][lm]=av.w;
        Bs[lk+0][lm]=bv.x; Bs[lk+1][lm]=bv.y; Bs[lk+2][lm]=bv.z; Bs[lk+3][lm]=bv.w;
        __syncthreads();
#pragma unroll
        for (int k = 0; k < 16; k++) {
            float4 a4 = *(const float4*)&As[k][ty << 2];
            float4 b4 = *(const float4*)&Bs[k][tx << 2];
            float aa[4] = {a4.x, a4.y, a4.z, a4.w};
            float bb[4] = {b4.x, b4.y, b4.z, b4.w};
#pragma unroll
            for (int i = 0; i < 4; i++)
#pragma unroll
                for (int j = 0; j < 4; j++)
                    acc[i][j] = fmaf(aa[i], bb[j], acc[i][j]);
        }
        __syncthreads();
    }
#pragma unroll
    for (int i = 0; i < 4; i++) {
        int r = r0 + (ty << 2) + i;
        if (r < cnt) {
            int pair = g_perm[base + r];
            float w = g_topkw[pair];
            float* yrow = g_y + (size_t)pair * D + d0 + (tx << 2);
#pragma unroll
            for (int j = 0; j < 4; j++) yrow[j] = w * acc[i][j];
        }
    }
}

// shared expert gate/up:  S[t,f] = silu(x_t . Wg[:,f]) * (x_t . Wu[:,f])   (B is K-major)
__global__ __launch_bounds__(256) void k_shared_gateup(const float* __restrict__ x,
                                                       const float* __restrict__ wg,
                                                       const float* __restrict__ wu) {
    int t0 = blockIdx.y * 64;
    int f0 = blockIdx.x * 64;
    __shared__ float As[16][68], Bg[16][68], Bu[16][68];
    int tid = threadIdx.x;
    int lm = tid >> 2;
    int lk = (tid & 3) << 2;
    const float* xrow = x + (size_t)(t0 + lm) * D;
    int kl = tid >> 4;               // 0..15
    int fq = (tid & 15) << 2;        // 0..60

    int ty = tid >> 4, tx = tid & 15;
    float ag[4][4] = {}, au[4][4] = {};

    for (int k0 = 0; k0 < D; k0 += 16) {
        float4 av = *(const float4*)(xrow + k0 + lk);
        As[lk+0][lm]=av.x; As[lk+1][lm]=av.y; As[lk+2][lm]=av.z; As[lk+3][lm]=av.w;
        *(float4*)&Bg[kl][fq] = *(const float4*)(wg + (size_t)(k0 + kl) * FS + f0 + fq);
        *(float4*)&Bu[kl][fq] = *(const float4*)(wu + (size_t)(k0 + kl) * FS + f0 + fq);
        __syncthreads();
#pragma unroll
        for (int k = 0; k < 16; k++) {
            float4 a4 = *(const float4*)&As[k][ty << 2];
            float4 g4 = *(const float4*)&Bg[k][tx << 2];
            float4 u4 = *(const float4*)&Bu[k][tx << 2];
            float aa[4] = {a4.x, a4.y, a4.z, a4.w};
            float gg[4] = {g4.x, g4.y, g4.z, g4.w};
            float uu[4] = {u4.x, u4.y, u4.z, u4.w};
#pragma unroll
            for (int i = 0; i < 4; i++)
#pragma unroll
                for (int j = 0; j < 4; j++) {
                    ag[i][j] = fmaf(aa[i], gg[j], ag[i][j]);
                    au[i][j] = fmaf(aa[i], uu[j], au[i][j]);
                }
        }
        __syncthreads();
    }
#pragma unroll
    for (int i = 0; i < 4; i++) {
        int t = t0 + (ty << 2) + i;
        float* srow = g_s + (size_t)t * FS + f0 + (tx << 2);
#pragma unroll
        for (int j = 0; j < 4; j++) {
            float g = ag[i][j], u = au[i][j];
            float sig = 1.f / (1.f + __expf(-g));
            srow[j] = g * sig * u;
        }
    }
}

// shared expert down:  SH[t,d] = S[t,:] . Wd[:,d]   (B is K-major)
__global__ __launch_bounds__(256) void k_shared_down(const float* __restrict__ wd) {
    int t0 = blockIdx.y * 64;
    int d0 = blockIdx.x * 64;
    __shared__ float As[16][68], Bs[16][68];
    int tid = threadIdx.x;
    int lm = tid >> 2;
    int lk = (tid & 3) << 2;
    const float* srow = g_s + (size_t)(t0 + lm) * FS;
    int kl = tid >> 4;
    int fq = (tid & 15) << 2;

    int ty = tid >> 4, tx = tid & 15;
    float acc[4][4] = {};

    for (int k0 = 0; k0 < FS; k0 += 16) {
        float4 av = *(const float4*)(srow + k0 + lk);
        As[lk+0][lm]=av.x; As[lk+1][lm]=av.y; As[lk+2][lm]=av.z; As[lk+3][lm]=av.w;
        *(float4*)&Bs[kl][fq] = *(const float4*)(wd + (size_t)(k0 + kl) * D + d0 + fq);
        __syncthreads();
#pragma unroll
        for (int k = 0; k < 16; k++) {
            float4 a4 = *(const float4*)&As[k][ty << 2];
            float4 b4 = *(const float4*)&Bs[k][tx << 2];
            float aa[4] = {a4.x, a4.y, a4.z, a4.w};
            float bb[4] = {b4.x, b4.y, b4.z, b4.w};
#pragma unroll
            for (int i = 0; i < 4; i++)
#pragma unroll
                for (int j = 0; j < 4; j++)
                    acc[i][j] = fmaf(aa[i], bb[j], acc[i][j]);
        }
        __syncthreads();
    }
#pragma unroll
    for (int i = 0; i < 4; i++) {
        int t = t0 + (ty << 2) + i;
        float* orow = g_sh + (size_t)t * D + d0 + (tx << 2);
#pragma unroll
        for (int j = 0; j < 4; j++) orow[j] = acc[i][j];
    }
}

// out[t,d] = y0 + y1 + sgate * shared     (routing weights already applied)
__global__ void k_combine(float* __restrict__ out) {
    int i = blockIdx.x * blockDim.x + threadIdx.x;
    if (i >= NTOK * (D / 4)) return;
    int t = i >> 8;              // D/4 = 256
    int c = (i & 255) << 2;
    float4 y0 = *(const float4*)(g_y + (size_t)(2 * t + 0) * D + c);
    float4 y1 = *(const float4*)(g_y + (size_t)(2 * t + 1) * D + c);
    float4 sh = *(const float4*)(g_sh + (size_t)t * D + c);
    float sg = g_sgate[t];
    float4 o;
    o.x = y0.x + y1.x + sg * sh.x;
    o.y = y0.y + y1.y + sg * sh.y;
    o.z = y0.z + y1.z + sg * sh.z;
    o.w = y0.w + y1.w + sg * sh.w;
    *(float4*)(out + (size_t)t * D + c) = o;
}

// deterministic aux-loss reduction (fixed-order tree)
__global__ void k_aux(float* __restrict__ out, int out_size) {
    __shared__ float sred[256];
    float le[E];
#pragma unroll
    for (int e = 0; e < E; e++) le[e] = 0.f;
    for (int t = threadIdx.x; t < NTOK; t += 256)
#pragma unroll
        for (int e = 0; e < E; e++) le[e] += g_probs[(size_t)t * E + e];

    float aux = 0.f;
    for (int e = 0; e < E; e++) {
        sred[threadIdx.x] = le[e];
        __syncthreads();
        for (int s = 128; s; s >>= 1) {
            if (threadIdx.x < s) sred[threadIdx.x] += sred[threadIdx.x + s];
            __syncthreads();
        }
        if (threadIdx.x == 0) {
            float load = sred[0] * (1.f / NTOK);
            float d = load - (1.f / E);
            aux += d * d;
        }
        __syncthreads();
    }
    if (threadIdx.x == 0 && out_size > NTOK * D)
        out[NTOK * D] = 0.001f * aux;
}

// ---------------- launch -----------------------------------------------------
extern "C" void kernel_launch(void* const* d_in, const int* in_sizes, int n_in,
                              void* d_out, int out_size) {
    const float* x   = (const float*)d_in[0];   // [B,T,D]
    const float* gup = (const float*)d_in[1];   // [E,2F,D]
    const float* dwn = (const float*)d_in[2];   // [E,D,F]
    const float* rw  = (const float*)d_in[3];   // [D,E]
    const float* shg = (const float*)d_in[4];   // [D,FS]
    const float* shu = (const float*)d_in[5];   // [D,FS]
    const float* shd = (const float*)d_in[6];   // [FS,D]
    const float* sgw = (const float*)d_in[7];   // [D,1]
    float* out = (float*)d_out;

    k_zero<<<1, 32>>>();
    k_router<<<NTOK / 4, 128>>>(x, rw, sgw);
    k_scan<<<1, 1>>>();
    k_scatter<<<P / 256, 256>>>();
    k_expert_gateup<<<dim3(F / 64, P / 64, E), 256>>>(x, gup);
    k_expert_down<<<dim3(D / 64, P / 64, E), 256>>>(dwn);
    k_shared_gateup<<<dim3(FS / 64, NTOK / 64), 256>>>(x, shg, shu);
    k_shared_down<<<dim3(D / 64, NTOK / 64), 256>>>(shd);
    k_combine<<<(NTOK * (D / 4) + 255) / 256, 256>>>(out);
    k_aux<<<1, 256>>>(out, out_size);
}